// round 9
// baseline (speedup 1.0000x reference)
#include <cuda_runtime.h>
#include <math.h>

#define NSEG 4
#define NPIX 256
#define NTHR 1024
#define TSX 16
#define TSY 16
#define NB  148
#define MAXNV 64

// Monotonic per-view work-queue tickets (replay-safe: each launch consumes
// exactly tilesPerView + blocksPerView tickets per view; never reset).
__device__ unsigned int g_q[MAXNV];

// ---------------------------------------------------------------------------
// Single kernel. Each block serves ONE view: preps all G gaussians into smem
// once, then dynamically grabs tiles (cull -> warp rank sort -> blend).
// ---------------------------------------------------------------------------
__global__ __launch_bounds__(NTHR, 1)
void splat_kernel(float* __restrict__ out,
                  const float* __restrict__ means,
                  const float* __restrict__ scales,
                  const float* __restrict__ rots,
                  const float* __restrict__ sh,
                  const float* __restrict__ opac,
                  const float* __restrict__ extr,
                  const float* __restrict__ intr,
                  const int* __restrict__ Hp,
                  const int* __restrict__ Wp,
                  int G, int NV)
{
    int W = *Wp, H = *Hp;
    int ntx = (W + TSX - 1) / TSX, nty = (H + TSY - 1) / TSY;
    int tilesPerView = ntx * nty;
    int tid = threadIdx.x;
    int lane = tid & 31;
    int wid = tid >> 5;

    extern __shared__ char dsm[];
    float4* s_pos = (float4*)dsm;                   // (u, v, thr, z)   G*16
    float4* s_con = s_pos + G;                      // (ca, cb, cc, op) G*16
    float4* s_col = s_con + G;                      // (cr, cg, cb, -)  G*16
    float*  s_rad = (float*)(s_col + G);            // cull radius      G*4
    unsigned long long* s_key = (unsigned long long*)(s_rad + G);  // G*8
    int* s_sid = (int*)(s_key + G);                 // sorted order     G*4
    __shared__ float4 segC[NSEG][NPIX];
    __shared__ float  segT[NSEG][NPIX];
    __shared__ int s_cnt;
    __shared__ int s_tile;

    for (int vi = 0; vi < NV; vi++) {
        int b0 = (int)((long long)vi * NB / NV);
        int b1 = (int)((long long)(vi + 1) * NB / NV);
        if ((int)blockIdx.x < b0 || (int)blockIdx.x >= b1) continue;
        int nbv = b1 - b0;
        unsigned int M = (unsigned int)(tilesPerView + nbv);  // ticket window

        const float* E = extr + vi * 16;
        const float* K = intr + vi * 9;
        float Wf = (float)W, Hf = (float)H;
        float fx = (K[0] / Wf) * Wf;
        float cx = (K[2] / Wf) * Wf;
        float fy = (K[4] / Hf) * Hf;
        float cy = (K[5] / Hf) * Hf;

        // ================= Phase A: prep all G gaussians into smem =========
        for (int g = tid; g < G; g += NTHR) {
            float mx = means[g*3+0], my = means[g*3+1], mz = means[g*3+2];
            float px = E[0]*mx + E[1]*my + E[2]*mz  + E[3];
            float py = E[4]*mx + E[5]*my + E[6]*mz  + E[7];
            float pz = E[8]*mx + E[9]*my + E[10]*mz + E[11];
            float zs = fmaxf(pz, 1e-6f);
            float iz = 1.0f / zs;                  // single reciprocal, reused
            float u = fx * px * iz + cx;
            float v = fy * py * iz + cy;

            float4 q4 = ((const float4*)rots)[g];
            float qw = q4.x, qx = q4.y, qy = q4.z, qz = q4.w;
            float qinv = rsqrtf(qw*qw + qx*qx + qy*qy + qz*qz);
            qw *= qinv; qx *= qinv; qy *= qinv; qz *= qinv;
            float R00 = 1.f - 2.f*(qy*qy + qz*qz), R01 = 2.f*(qx*qy - qw*qz), R02 = 2.f*(qx*qz + qw*qy);
            float R10 = 2.f*(qx*qy + qw*qz), R11 = 1.f - 2.f*(qx*qx + qz*qz), R12 = 2.f*(qy*qz - qw*qx);
            float R20 = 2.f*(qx*qz - qw*qy), R21 = 2.f*(qy*qz + qw*qx), R22 = 1.f - 2.f*(qx*qx + qy*qy);

            float s0 = scales[g*3+0], s1 = scales[g*3+1], s2 = scales[g*3+2];
            float M00=R00*s0, M01=R01*s1, M02=R02*s2;
            float M10=R10*s0, M11=R11*s1, M12=R12*s2;
            float M20=R20*s0, M21=R21*s1, M22=R22*s2;
            float S00 = M00*M00+M01*M01+M02*M02;
            float S01 = M00*M10+M01*M11+M02*M12;
            float S02 = M00*M20+M01*M21+M02*M22;
            float S11 = M10*M10+M11*M11+M12*M12;
            float S12 = M10*M20+M11*M21+M12*M22;
            float S22 = M20*M20+M21*M21+M22*M22;

            float J00 = fx*iz,  J02 = -fx*px*iz*iz;
            float J11 = fy*iz,  J12 = -fy*py*iz*iz;
            float t00 = J00*E[0] + J02*E[8];
            float t01 = J00*E[1] + J02*E[9];
            float t02 = J00*E[2] + J02*E[10];
            float t10 = J11*E[4] + J12*E[8];
            float t11 = J11*E[5] + J12*E[9];
            float t12 = J11*E[6] + J12*E[10];
            float w0 = S00*t00 + S01*t01 + S02*t02;
            float w1 = S01*t00 + S11*t01 + S12*t02;
            float w2 = S02*t00 + S12*t01 + S22*t02;
            float a  = t00*w0 + t01*w1 + t02*w2 + 0.3f;
            float b  = t10*w0 + t11*w1 + t12*w2;
            float x0 = S00*t10 + S01*t11 + S02*t12;
            float x1 = S01*t10 + S11*t11 + S12*t12;
            float x2 = S02*t10 + S12*t11 + S22*t12;
            float d  = t10*x0 + t11*x1 + t12*x2 + 0.3f;

            float det = a*d - b*b;
            float ds  = fmaxf(det, 1e-12f);
            float ids = 1.0f / ds;
            bool valid = (pz > 0.2f) && (det > 1e-12f);
            float op = valid ? opac[g] : 0.f;

            const float SH_C0 = 0.28209479177387814f;
            float cr  = fmaxf(SH_C0 * sh[g*3+0] + 0.5f, 0.f);
            float cg  = fmaxf(SH_C0 * sh[g*3+1] + 0.5f, 0.f);
            float cbl = fmaxf(SH_C0 * sh[g*3+2] + 0.5f, 0.f);

            // conservative cull radius (1/255 bound via lmax(cov2D));
            // __logf err ~1e-7 rel, swamped by +0.05 / 1e-4 safety margins
            float rad = -1.f, thr = 0.f;
            if (op * 255.f > 1.f) {
                float lam = 0.5f*(a+d) + sqrtf(0.25f*(a-d)*(a-d) + b*b);
                float t = __logf(255.f * op);
                rad = sqrtf(fmaxf(2.f*t*lam, 0.f)) + 0.05f;
                thr = -t - 1e-4f;   // power < thr => alpha < 1/255 guaranteed
            }

            s_pos[g] = make_float4(u, v, thr, pz);
            s_con[g] = make_float4(-0.5f*d*ids, b*ids, -0.5f*a*ids, op);
            s_col[g] = make_float4(cr, cg, cbl, 0.f);
            s_rad[g] = rad;
        }
        __syncthreads();

        // ================= Phase B: dynamic tile queue =====================
        int seg = tid >> 8, pix = tid & (NPIX - 1);
        int lx = pix & (TSX - 1), ly = pix >> 4;

        while (true) {
            __syncthreads();
            if (tid == 0) {
                unsigned int tk = atomicAdd(&g_q[vi], 1u);
                s_tile = (int)(tk % M);        // >= tilesPerView -> exit ticket
                s_cnt = 0;
            }
            __syncthreads();
            int t2 = s_tile;
            if (t2 >= tilesPerView) break;

            int tx = t2 % ntx, ty = t2 / ntx;
            float tminx = (float)(tx*TSX), tmaxx = (float)(tx*TSX + TSX);
            float tminy = (float)(ty*TSY), tmaxy = (float)(ty*TSY + TSY);

            // ---- cull from smem: append (flipped z | idx) keys ----
            for (int g = tid; g < G; g += NTHR) {
                float4 p = s_pos[g];
                float rad = s_rad[g];
                bool keep = (rad > 0.f &&
                             p.x >= tminx - rad && p.x <= tmaxx + rad &&
                             p.y >= tminy - rad && p.y <= tmaxy + rad);
                unsigned m = __ballot_sync(0xffffffffu, keep);
                if (m) {
                    int leader = __ffs(m) - 1;
                    int basep = 0;
                    if (lane == leader) basep = atomicAdd(&s_cnt, __popc(m));
                    basep = __shfl_sync(0xffffffffu, basep, leader);
                    if (keep) {
                        unsigned int zb = __float_as_uint(p.w);
                        zb = (zb & 0x80000000u) ? ~zb : (zb | 0x80000000u);
                        int pp = basep + __popc(m & ((1u << lane) - 1u));
                        s_key[pp] = ((unsigned long long)zb << 32) | (unsigned int)g;
                    }
                }
            }
            __syncthreads();
            int cnt = s_cnt;

            // ---- warp-parallel exact rank sort (unique keys) ----
            for (int i = wid; i < cnt; i += 32) {
                unsigned long long k = s_key[i];
                int r = 0;
                for (int j = lane; j < cnt; j += 32) r += (s_key[j] < k);
                r = __reduce_add_sync(0xffffffffu, r);
                if (lane == 0) s_sid[r] = (int)(unsigned int)k;
            }
            __syncthreads();

            // ---- segment-parallel blend via sorted-index indirection ----
            float pcx = (float)(tx*TSX + lx) + 0.5f;
            float pcy = (float)(ty*TSY + ly) + 0.5f;
            int L = (cnt + NSEG - 1) / NSEG;
            int j0 = seg * L;
            int j1 = min(j0 + L, cnt);

            float T = 1.f, ar = 0.f, ag = 0.f, ab = 0.f, ad = 0.f;
            for (int j = j0; j < j1; j++) {
                int idx = s_sid[j];                 // broadcast LDS
                float4 p  = s_pos[idx];
                float4 cn = s_con[idx];
                float du = pcx - p.x, dv = pcy - p.y;
                float power = fmaf(cn.x, du*du, fmaf(cn.z, dv*dv, cn.y*du*dv));
                if (power < p.z) continue;          // alpha < 1/255 guaranteed
                power = fminf(power, 0.f);
                float alpha = fminf(cn.w * __expf(power), 0.99f);
                if (alpha >= (1.0f/255.0f)) {
                    float4 cl = s_col[idx];
                    float w = alpha * T;
                    ar += w * cl.x; ag += w * cl.y; ab += w * cl.z;
                    ad += w * p.w;
                    T *= (1.f - alpha);
                    if (T < 1e-5f) break;           // residual < 1e-5 absolute
                }
            }
            segC[seg][pix] = make_float4(ar, ag, ab, ad);
            segT[seg][pix] = T;
            __syncthreads();

            // ---- combine segments front-to-back + store ----
            if (seg == 0) {
                float4 C = segC[0][pix];
                float Tacc = segT[0][pix];
                #pragma unroll
                for (int s = 1; s < NSEG; s++) {
                    float4 Cs = segC[s][pix];
                    C.x += Tacc * Cs.x; C.y += Tacc * Cs.y;
                    C.z += Tacc * Cs.z; C.w += Tacc * Cs.w;
                    Tacc *= segT[s][pix];
                }
                int px = tx*TSX + lx, py = ty*TSY + ly;
                if (px < W && py < H) {
                    ((float4*)out)[(vi * H + py) * W + px] = C;
                }
            }
        }
        break;   // each block serves exactly one view
    }
}

// ---------------------------------------------------------------------------
extern "C" void kernel_launch(void* const* d_in, const int* in_sizes, int n_in,
                              void* d_out, int out_size)
{
    const float* means  = (const float*)d_in[0];
    const float* scales = (const float*)d_in[1];
    const float* rots   = (const float*)d_in[2];
    const float* sh     = (const float*)d_in[3];
    const float* opac   = (const float*)d_in[4];
    const float* extr   = (const float*)d_in[5];
    const float* intr   = (const float*)d_in[6];
    const int*   Hp     = (const int*)d_in[7];
    const int*   Wp     = (const int*)d_in[8];
    float* out = (float*)d_out;

    int G  = in_sizes[4];        // B = 1 for this instance
    int NV = in_sizes[5] / 16;   // B*N views

    // pos + con + col + rad + key + sid = 48 + 4 + 8 + 4 = 64 B per gaussian
    size_t dynSmem = (size_t)G * 64;
    static int attrSet = 0;
    if (!attrSet) {
        cudaFuncSetAttribute(splat_kernel,
                             cudaFuncAttributeMaxDynamicSharedMemorySize,
                             (int)dynSmem);
        attrSet = 1;
    }
    splat_kernel<<<NB, NTHR, dynSmem>>>(out, means, scales, rots, sh, opac,
                                        extr, intr, Hp, Wp, G, NV);
}